// round 14
// baseline (speedup 1.0000x reference)
#include <cuda_runtime.h>
#include <cuda_fp16.h>
#include <mma.h>
#include <math.h>

using namespace nvcuda;

#define NN   262144
#define HD   64
#define DGI  5
#define DSI  6
#define OD   8
#define EGGMAX 4000000
#define EHMAX  2000000
#define EINMAX 2000000
#define ESSMAX 2000000
#define NGROUPS (NN / 4)
#define NTILES (NN / 16)

// ---------------- scratch (device globals; no allocs) -------------------------
__device__ int   g_is64[4];
__device__ int   g_hist_gg[NN], g_hist_h[NN], g_hist_in[NN], g_hist_ss[NN];
__device__ int   g_rp_gg[NN+1], g_rp_h[NN+1], g_rp_in[NN+1], g_rp_ss[NN+1];
__device__ int   g_cur0[NN], g_cur1[NN], g_cur2[NN], g_cur3[NN];
__device__ int   g_bsum0[512], g_bsum1[512], g_bsum2[512], g_bsum3[512];
__device__ int   g_src_gg[EGGMAX];  __device__ float g_w_gg[EGGMAX];
__device__ int   g_src_h [EHMAX];   __device__ float g_w_h [EHMAX];
__device__ int   g_src_in[EINMAX];
__device__ int2  g_csr_ss[ESSMAX];          // packed (src, w) for ss edges
__device__ float g_dinv1[NN], g_dinv2[NN];
// fp16 feature arrays
__device__ __half g_xg16[NN*8];
__device__ __half g_x1h[NN*8], g_x2h[NN*8];
__device__ __half g_gamex16[NN*HD];
__device__ __half g_agg1h[NN*HD];
__device__ __half g_agg2h[NN*HD];
__device__ __half g_state1h[NN*HD];
__device__ __half g_state2h[NN*HD];
__device__ __half g_h1h[NN*HD], g_h2h[NN*HD], g_h3h[NN*HD];
// pre-converted fp16 tag2 weights
__device__ __half g_tw16[4*HD*HD];

// ---------------- dtype detection ---------------------------------------------
__global__ void k_detect(const unsigned* a0, const unsigned* a1,
                         const unsigned* a2, const unsigned* a3) {
    const unsigned* arr[4] = {a0, a1, a2, a3};
    int i = threadIdx.x;
    if (i < 4) {
        const unsigned* p = arr[i];
        int ok = 1;
        for (int k = 0; k < 64; k++) if (p[2*k+1] != 0u) { ok = 0; break; }
        g_is64[i] = ok;
    }
}

__device__ __forceinline__ int fetch_col(const void* p, int E, int is64, int e) {
    if (is64) return (int)((const long long*)p)[(long)E + e];
    return ((const int*)p)[E + e];
}
__device__ __forceinline__ int fetch_row(const void* p, int E, int is64, int e) {
    if (is64) return (int)((const long long*)p)[e];
    return ((const int*)p)[e];
}

// ---------------- CSR build ---------------------------------------------------
__global__ void k_hist(const void* p, int E, int flag, int* __restrict__ hist) {
    int e = blockIdx.x * blockDim.x + threadIdx.x;
    if (e >= E) return;
    int is64 = g_is64[flag];
    atomicAdd(&hist[fetch_col(p, E, is64, e)], 1);
}

// scan1 fused with dinv (optional): dinv[i] = rsqrt(hist[i]) while scanning
__global__ void k_scan1d(const int* __restrict__ hist, int* __restrict__ rp,
                         int* __restrict__ bsum, float* __restrict__ dinv) {
    __shared__ int sh[512];
    int t = threadIdx.x;
    int i = blockIdx.x * 512 + t;
    int v = hist[i];
    if (dinv) dinv[i] = v > 0 ? rsqrtf((float)v) : 0.f;
    sh[t] = v; __syncthreads();
    for (int o = 1; o < 512; o <<= 1) {
        int tmp = (t >= o) ? sh[t - o] : 0;
        __syncthreads();
        sh[t] += tmp;
        __syncthreads();
    }
    rp[i] = sh[t] - v;
    if (t == 511) bsum[blockIdx.x] = sh[511];
}

// fused: every block redundantly scans block-sums, adds offset, writes cursor
__global__ void k_scan23(int* __restrict__ rp, int* __restrict__ cur,
                         const int* __restrict__ bsum, int E) {
    __shared__ int sh[512];
    int t = threadIdx.x;
    sh[t] = bsum[t];
    __syncthreads();
    for (int o = 1; o < 512; o <<= 1) {
        int tmp = (t >= o) ? sh[t - o] : 0;
        __syncthreads();
        sh[t] += tmp;
        __syncthreads();
    }
    int add = (blockIdx.x > 0) ? sh[blockIdx.x - 1] : 0;
    int i = blockIdx.x * 512 + t;
    int v = rp[i] + add;
    rp[i] = v;
    cur[i] = v;
    if (i == NN - 1) rp[NN] = E;
}

template<int WMODE>
__global__ void k_place(const void* p, int E, int flag, int* __restrict__ cursor,
                        int* __restrict__ csr_src, float* __restrict__ csr_w,
                        const float* __restrict__ dinv, const float* __restrict__ ew) {
    int e = blockIdx.x * blockDim.x + threadIdx.x;
    if (e >= E) return;
    int is64 = g_is64[flag];
    int r = fetch_row(p, E, is64, e);
    int c = fetch_col(p, E, is64, e);
    int pos = atomicAdd(&cursor[c], 1);
    csr_src[pos] = r;
    if (WMODE == 0) csr_w[pos] = dinv[r];
    if (WMODE == 1) csr_w[pos] = ew[e];
}

// ss-only: packed (src, dinv[src]) int2 store
__global__ void k_place_ss(const void* p, int E, int flag, int* __restrict__ cursor,
                           int2* __restrict__ csr, const float* __restrict__ dinv) {
    int e = blockIdx.x * blockDim.x + threadIdx.x;
    if (e >= E) return;
    int is64 = g_is64[flag];
    int r = fetch_row(p, E, is64, e);
    int c = fetch_col(p, E, is64, e);
    int pos = atomicAdd(&cursor[c], 1);
    int2 v; v.x = r; v.y = __float_as_int(dinv[r]);
    csr[pos] = v;
}

// ---------------- weight preconversion + pack5 --------------------------------
__global__ void k_cvtw(const float* __restrict__ w) {
    int i = blockIdx.x * blockDim.x + threadIdx.x;
    g_tw16[i] = __float2half(w[i]);
}

__global__ void k_pack5(const float* __restrict__ x, __half* __restrict__ o) {
    int i = blockIdx.x * blockDim.x + threadIdx.x;
    if (i >= NN) return;
    const float* r = x + (long)i * DGI;
    __half h[8];
#pragma unroll
    for (int k = 0; k < 5; k++) h[k] = __float2half(r[k]);
    h[5] = h[6] = h[7] = __float2half(0.f);
    ((uint4*)o)[i] = *(uint4*)h;
}

// ---------------- pull: dim-5 TAG hop (8 lanes/node, 2-edge unroll) -----------
__global__ void k_pull5(const int* __restrict__ rp, const int* __restrict__ csr_src,
                        const float* __restrict__ csr_w, const float* __restrict__ dinv,
                        const __half* __restrict__ xin, __half* __restrict__ xout) {
    int tid = blockIdx.x * blockDim.x + threadIdx.x;
    int node = tid >> 3, sub = tid & 7;
    int s = rp[node], e = rp[node + 1];
    float a0 = 0, a1 = 0, a2 = 0, a3 = 0, a4 = 0;
    int i = s + sub;
    for (; i + 8 < e; i += 16) {
        int r0 = csr_src[i], r1 = csr_src[i + 8];
        float w0 = csr_w[i], w1 = csr_w[i + 8];
        uint4 u0 = ((const uint4*)xin)[r0];
        uint4 u1 = ((const uint4*)xin)[r1];
        __half2* hp0 = (__half2*)&u0;
        __half2* hp1 = (__half2*)&u1;
        float2 p00 = __half22float2(hp0[0]), p01 = __half22float2(hp0[1]);
        float2 p02 = __half22float2(hp0[2]);
        float2 p10 = __half22float2(hp1[0]), p11 = __half22float2(hp1[1]);
        float2 p12 = __half22float2(hp1[2]);
        a0 = fmaf(w0, p00.x, a0); a1 = fmaf(w0, p00.y, a1);
        a2 = fmaf(w0, p01.x, a2); a3 = fmaf(w0, p01.y, a3);
        a4 = fmaf(w0, p02.x, a4);
        a0 = fmaf(w1, p10.x, a0); a1 = fmaf(w1, p10.y, a1);
        a2 = fmaf(w1, p11.x, a2); a3 = fmaf(w1, p11.y, a3);
        a4 = fmaf(w1, p12.x, a4);
    }
    if (i < e) {
        int r = csr_src[i];
        float w = csr_w[i];
        uint4 u = ((const uint4*)xin)[r];
        __half2* hp = (__half2*)&u;
        float2 p0 = __half22float2(hp[0]);
        float2 p1 = __half22float2(hp[1]);
        float2 p2 = __half22float2(hp[2]);
        a0 = fmaf(w, p0.x, a0); a1 = fmaf(w, p0.y, a1);
        a2 = fmaf(w, p1.x, a2); a3 = fmaf(w, p1.y, a3);
        a4 = fmaf(w, p2.x, a4);
    }
#pragma unroll
    for (int o = 4; o; o >>= 1) {
        a0 += __shfl_down_sync(0xffffffffu, a0, o, 8);
        a1 += __shfl_down_sync(0xffffffffu, a1, o, 8);
        a2 += __shfl_down_sync(0xffffffffu, a2, o, 8);
        a3 += __shfl_down_sync(0xffffffffu, a3, o, 8);
        a4 += __shfl_down_sync(0xffffffffu, a4, o, 8);
    }
    if (sub == 0) {
        float dc = dinv[node];
        __half h[8];
        h[0] = __float2half(dc * a0); h[1] = __float2half(dc * a1);
        h[2] = __float2half(dc * a2); h[3] = __float2half(dc * a3);
        h[4] = __float2half(dc * a4);
        h[5] = h[6] = h[7] = __float2half(0.f);
        ((uint4*)xout)[node] = *(uint4*)h;
    }
}

// ---------------- pull: dim-64 hop (16 lanes/node, 4-edge unroll) -------------
// MODE 1: weighted (GraphConv);  MODE 2: unweighted mean (SAGE)
template<int MODE>
__global__ void __launch_bounds__(256)
k_pull64(const int* __restrict__ rp, const int* __restrict__ csr_src,
         const float* __restrict__ csr_w, const float* __restrict__ dinv,
         const __half* __restrict__ xin, __half* __restrict__ xout) {
    int gtid = blockIdx.x * blockDim.x + threadIdx.x;
    int node = gtid >> 4;
    int l16 = threadIdx.x & 15;
    int s = rp[node], e = rp[node + 1];
    float ax = 0.f, ay = 0.f, az = 0.f, aw = 0.f;
    int i = s;
    for (; i + 3 < e; i += 4) {
        int r0 = csr_src[i],     r1 = csr_src[i + 1];
        int r2 = csr_src[i + 2], r3 = csr_src[i + 3];
        uint2 u0 = ((const uint2*)(xin + (size_t)r0 * HD))[l16];
        uint2 u1 = ((const uint2*)(xin + (size_t)r1 * HD))[l16];
        uint2 u2 = ((const uint2*)(xin + (size_t)r2 * HD))[l16];
        uint2 u3 = ((const uint2*)(xin + (size_t)r3 * HD))[l16];
        __half2* h0 = (__half2*)&u0; __half2* h1 = (__half2*)&u1;
        __half2* h2 = (__half2*)&u2; __half2* h3 = (__half2*)&u3;
        float2 f0a = __half22float2(h0[0]), f0b = __half22float2(h0[1]);
        float2 f1a = __half22float2(h1[0]), f1b = __half22float2(h1[1]);
        float2 f2a = __half22float2(h2[0]), f2b = __half22float2(h2[1]);
        float2 f3a = __half22float2(h3[0]), f3b = __half22float2(h3[1]);
        if (MODE == 2) {
            ax += (f0a.x + f1a.x) + (f2a.x + f3a.x);
            ay += (f0a.y + f1a.y) + (f2a.y + f3a.y);
            az += (f0b.x + f1b.x) + (f2b.x + f3b.x);
            aw += (f0b.y + f1b.y) + (f2b.y + f3b.y);
        } else {
            float w0 = csr_w[i],     w1 = csr_w[i + 1];
            float w2 = csr_w[i + 2], w3 = csr_w[i + 3];
            ax = fmaf(w0, f0a.x, ax); ay = fmaf(w0, f0a.y, ay);
            az = fmaf(w0, f0b.x, az); aw = fmaf(w0, f0b.y, aw);
            ax = fmaf(w1, f1a.x, ax); ay = fmaf(w1, f1a.y, ay);
            az = fmaf(w1, f1b.x, az); aw = fmaf(w1, f1b.y, aw);
            ax = fmaf(w2, f2a.x, ax); ay = fmaf(w2, f2a.y, ay);
            az = fmaf(w2, f2b.x, az); aw = fmaf(w2, f2b.y, aw);
            ax = fmaf(w3, f3a.x, ax); ay = fmaf(w3, f3a.y, ay);
            az = fmaf(w3, f3b.x, az); aw = fmaf(w3, f3b.y, aw);
        }
    }
    for (; i < e; i++) {
        int r0 = csr_src[i];
        uint2 u0 = ((const uint2*)(xin + (size_t)r0 * HD))[l16];
        __half2* h0 = (__half2*)&u0;
        float2 f0a = __half22float2(h0[0]), f0b = __half22float2(h0[1]);
        if (MODE == 2) { ax += f0a.x; ay += f0a.y; az += f0b.x; aw += f0b.y; }
        else {
            float w0 = csr_w[i];
            ax = fmaf(w0, f0a.x, ax); ay = fmaf(w0, f0a.y, ay);
            az = fmaf(w0, f0b.x, az); aw = fmaf(w0, f0b.y, aw);
        }
    }
    if (MODE == 2) {
        int c = e - s;
        if (c > 0) { float inv = 1.f / (float)c; ax *= inv; ay *= inv; az *= inv; aw *= inv; }
    }
    __half2 o0 = __floats2half2_rn(ax, ay);
    __half2 o1 = __floats2half2_rn(az, aw);
    uint2 u;
    u.x = *(unsigned*)&o0; u.y = *(unsigned*)&o1;
    ((uint2*)(xout + (size_t)node * HD))[l16] = u;
}

// ---------------- pull: dim-64 TAG hop (ss), packed int2 CSR ------------------
__global__ void __launch_bounds__(256)
k_pull64_ss(const int* __restrict__ rp, const int2* __restrict__ csr,
            const float* __restrict__ dinv,
            const __half* __restrict__ xin, __half* __restrict__ xout) {
    int gtid = blockIdx.x * blockDim.x + threadIdx.x;
    int node = gtid >> 4;
    int l16 = threadIdx.x & 15;
    int s = rp[node], e = rp[node + 1];
    float ax = 0.f, ay = 0.f, az = 0.f, aw = 0.f;
    int i = s;
    for (; i + 3 < e; i += 4) {
        int2 c0 = csr[i],     c1 = csr[i + 1];
        int2 c2 = csr[i + 2], c3 = csr[i + 3];
        uint2 u0 = ((const uint2*)(xin + (size_t)c0.x * HD))[l16];
        uint2 u1 = ((const uint2*)(xin + (size_t)c1.x * HD))[l16];
        uint2 u2 = ((const uint2*)(xin + (size_t)c2.x * HD))[l16];
        uint2 u3 = ((const uint2*)(xin + (size_t)c3.x * HD))[l16];
        __half2* h0 = (__half2*)&u0; __half2* h1 = (__half2*)&u1;
        __half2* h2 = (__half2*)&u2; __half2* h3 = (__half2*)&u3;
        float2 f0a = __half22float2(h0[0]), f0b = __half22float2(h0[1]);
        float2 f1a = __half22float2(h1[0]), f1b = __half22float2(h1[1]);
        float2 f2a = __half22float2(h2[0]), f2b = __half22float2(h2[1]);
        float2 f3a = __half22float2(h3[0]), f3b = __half22float2(h3[1]);
        float w0 = __int_as_float(c0.y), w1 = __int_as_float(c1.y);
        float w2 = __int_as_float(c2.y), w3 = __int_as_float(c3.y);
        ax = fmaf(w0, f0a.x, ax); ay = fmaf(w0, f0a.y, ay);
        az = fmaf(w0, f0b.x, az); aw = fmaf(w0, f0b.y, aw);
        ax = fmaf(w1, f1a.x, ax); ay = fmaf(w1, f1a.y, ay);
        az = fmaf(w1, f1b.x, az); aw = fmaf(w1, f1b.y, aw);
        ax = fmaf(w2, f2a.x, ax); ay = fmaf(w2, f2a.y, ay);
        az = fmaf(w2, f2b.x, az); aw = fmaf(w2, f2b.y, aw);
        ax = fmaf(w3, f3a.x, ax); ay = fmaf(w3, f3a.y, ay);
        az = fmaf(w3, f3b.x, az); aw = fmaf(w3, f3b.y, aw);
    }
    for (; i < e; i++) {
        int2 c0 = csr[i];
        uint2 u0 = ((const uint2*)(xin + (size_t)c0.x * HD))[l16];
        __half2* h0 = (__half2*)&u0;
        float2 f0a = __half22float2(h0[0]), f0b = __half22float2(h0[1]);
        float w0 = __int_as_float(c0.y);
        ax = fmaf(w0, f0a.x, ax); ay = fmaf(w0, f0a.y, ay);
        az = fmaf(w0, f0b.x, az); aw = fmaf(w0, f0b.y, aw);
    }
    float d = dinv[node];
    ax *= d; ay *= d; az *= d; aw *= d;
    __half2 o0 = __floats2half2_rn(ax, ay);
    __half2 o1 = __floats2half2_rn(az, aw);
    uint2 u;
    u.x = *(unsigned*)&o0; u.y = *(unsigned*)&o1;
    ((uint2*)(xout + (size_t)node * HD))[l16] = u;
}

// ---------------- TAG1 combine (persistent scalar; tiny K) --------------------
__global__ void k_tag1_p(const float* __restrict__ xg, const float* __restrict__ w,
                         const float* __restrict__ b) {
    __shared__ float sW[3 * DGI * HD];
    __shared__ float sB[HD];
    int tid = threadIdx.x;
    for (int i = tid; i < 3 * DGI * HD; i += 256) sW[i] = w[i];
    if (tid < HD) sB[tid] = b[tid];
    __syncthreads();
    int nl = tid >> 6, j = tid & 63;
    for (int g = blockIdx.x; g < NGROUPS; g += gridDim.x) {
        int node = g * 4 + nl;
        float acc = sB[j];
        const float* x0 = xg + (long)node * DGI;
        uint4 u1 = ((const uint4*)g_x1h)[node];
        uint4 u2 = ((const uint4*)g_x2h)[node];
        __half* h1 = (__half*)&u1;
        __half* h2 = (__half*)&u2;
#pragma unroll
        for (int k = 0; k < DGI; k++) {
            acc = fmaf(x0[k],               sW[k * HD + j],             acc);
            acc = fmaf(__half2float(h1[k]), sW[(DGI + k) * HD + j],     acc);
            acc = fmaf(__half2float(h2[k]), sW[(2 * DGI + k) * HD + j], acc);
        }
        g_gamex16[(size_t)node * HD + j] = __float2half(fmaxf(acc, 0.f));
    }
}

// ---------------- GraphConv combine (wmma) ------------------------------------
__global__ void k_gc_w(const float* __restrict__ xs, const float* __restrict__ wrel,
                       const float* __restrict__ brel, const float* __restrict__ wroot) {
    __shared__ __half sWh[HD * HD];
    __shared__ float sWroot[DSI * HD];
    __shared__ float sB[HD];
    __shared__ float sOut[8][16 * HD];
    __shared__ float sXr[8][16 * DSI];
    int tid = threadIdx.x;
    int wid = tid >> 5, lane = tid & 31;
    for (int i = tid; i < HD * HD; i += 256) sWh[i] = __float2half(wrel[i]);
    for (int i = tid; i < DSI * HD; i += 256) sWroot[i] = wroot[i];
    if (tid < HD) sB[tid] = brel[tid];
    __syncthreads();

    wmma::fragment<wmma::matrix_b, 16, 16, 16, __half, wmma::row_major> bf;
    wmma::fragment<wmma::matrix_a, 16, 16, 16, __half, wmma::row_major> af;
    wmma::fragment<wmma::accumulator, 16, 16, 16, float> acc[4];

    for (int t = blockIdx.x * 8 + wid; t < NTILES; t += gridDim.x * 8) {
        const __half* arow = g_agg1h + (size_t)t * 16 * HD;
#pragma unroll
        for (int nn = 0; nn < 4; nn++) wmma::fill_fragment(acc[nn], 0.f);
#pragma unroll
        for (int kk = 0; kk < 4; kk++) {
            wmma::load_matrix_sync(af, arow + kk * 16, HD);
#pragma unroll
            for (int nn = 0; nn < 4; nn++) {
                wmma::load_matrix_sync(bf, sWh + kk * 16 * HD + nn * 16, HD);
                wmma::mma_sync(acc[nn], af, bf, acc[nn]);
            }
        }
#pragma unroll
        for (int nn = 0; nn < 4; nn++)
            wmma::store_matrix_sync(&sOut[wid][nn * 16], acc[nn], HD, wmma::mem_row_major);
        for (int i = lane; i < 16 * DSI; i += 32)
            sXr[wid][i] = xs[(size_t)t * 16 * DSI + i];
        __syncwarp();
        for (int idx = lane; idx < 16 * HD; idx += 32) {
            int n = idx >> 6, j = idx & 63;
            float v = sOut[wid][idx] + sB[j];
#pragma unroll
            for (int k = 0; k < DSI; k++)
                v = fmaf(sXr[wid][n * DSI + k], sWroot[k * HD + j], v);
            g_state1h[(size_t)t * 16 * HD + idx] = __float2half(fmaxf(v, 0.f));
        }
        __syncwarp();
    }
}

// ---------------- SAGE combine (wmma, dynamic smem) ---------------------------
#define SAGE_SMEM (HD*HD*2*2 + HD*4 + 8*16*HD*4)
__global__ void k_sage_w(const float* __restrict__ wl, const float* __restrict__ bl,
                         const float* __restrict__ wr) {
    extern __shared__ char dyn[];
    __half* sWl = (__half*)dyn;
    __half* sWr = sWl + HD * HD;
    float* sB   = (float*)(sWr + HD * HD);
    float* sOutBase = sB + HD;
    int tid = threadIdx.x;
    int wid = tid >> 5, lane = tid & 31;
    float* sOut = sOutBase + wid * 16 * HD;
    for (int i = tid; i < HD * HD; i += 256) {
        sWl[i] = __float2half(wl[i]);
        sWr[i] = __float2half(wr[i]);
    }
    if (tid < HD) sB[tid] = bl[tid];
    __syncthreads();

    wmma::fragment<wmma::matrix_b, 16, 16, 16, __half, wmma::row_major> bf;
    wmma::fragment<wmma::matrix_a, 16, 16, 16, __half, wmma::row_major> af;
    wmma::fragment<wmma::accumulator, 16, 16, 16, float> acc[4];

    for (int t = blockIdx.x * 8 + wid; t < NTILES; t += gridDim.x * 8) {
#pragma unroll
        for (int nn = 0; nn < 4; nn++) wmma::fill_fragment(acc[nn], 0.f);
        const __half* a0 = g_agg2h   + (size_t)t * 16 * HD;
        const __half* a1 = g_state1h + (size_t)t * 16 * HD;
#pragma unroll
        for (int kk = 0; kk < 4; kk++) {
            wmma::load_matrix_sync(af, a0 + kk * 16, HD);
#pragma unroll
            for (int nn = 0; nn < 4; nn++) {
                wmma::load_matrix_sync(bf, sWl + kk * 16 * HD + nn * 16, HD);
                wmma::mma_sync(acc[nn], af, bf, acc[nn]);
            }
        }
#pragma unroll
        for (int kk = 0; kk < 4; kk++) {
            wmma::load_matrix_sync(af, a1 + kk * 16, HD);
#pragma unroll
            for (int nn = 0; nn < 4; nn++) {
                wmma::load_matrix_sync(bf, sWr + kk * 16 * HD + nn * 16, HD);
                wmma::mma_sync(acc[nn], af, bf, acc[nn]);
            }
        }
#pragma unroll
        for (int nn = 0; nn < 4; nn++)
            wmma::store_matrix_sync(sOut + nn * 16, acc[nn], HD, wmma::mem_row_major);
        __syncwarp();
        for (int idx = lane; idx < 16 * HD; idx += 32) {
            int j = idx & 63;
            float v = sOut[idx] + sB[j];
            g_state2h[(size_t)t * 16 * HD + idx] = __float2half(fmaxf(v, 0.f));
        }
        __syncwarp();
    }
}

// ---------------- TAG2 combine + final linear (wmma, dynamic smem) ------------
#define T2_LD 68
#define T2F_SMEM (4*HD*HD*2 + HD*OD*4 + HD*4 + OD*4 + 8*16*T2_LD*4)
__global__ void k_tag2f_w(const float* __restrict__ b,
                          const float* __restrict__ lw, const float* __restrict__ lb,
                          float* __restrict__ out) {
    extern __shared__ char dyn[];
    __half* sW4 = (__half*)dyn;
    float* sLW = (float*)(sW4 + 4 * HD * HD);
    float* sB  = sLW + HD * OD;
    float* sLB = sB + HD;
    float* sOutBase = sLB + OD;
    int tid = threadIdx.x;
    int wid = tid >> 5, lane = tid & 31;
    float* sOut = sOutBase + wid * 16 * T2_LD;
    // fp16 weights pre-converted by k_cvtw -> bulk uint4 copy
    for (int i = tid; i < 4 * HD * HD / 8; i += 256)
        ((uint4*)sW4)[i] = ((const uint4*)g_tw16)[i];
    for (int i = tid; i < HD * OD; i += 256) sLW[i] = lw[i];
    if (tid < HD) sB[tid] = b[tid];
    if (tid < OD) sLB[tid] = lb[tid];
    __syncthreads();

    wmma::fragment<wmma::matrix_b, 16, 16, 16, __half, wmma::row_major> bf;
    wmma::fragment<wmma::matrix_a, 16, 16, 16, __half, wmma::row_major> af;
    wmma::fragment<wmma::accumulator, 16, 16, 16, float> acc[4];
    const __half* srcs[4] = {g_state2h, g_h1h, g_h2h, g_h3h};

    for (int t = blockIdx.x * 8 + wid; t < NTILES; t += gridDim.x * 8) {
#pragma unroll
        for (int nn = 0; nn < 4; nn++) wmma::fill_fragment(acc[nn], 0.f);
#pragma unroll
        for (int h = 0; h < 4; h++) {
            const __half* arow = srcs[h] + (size_t)t * 16 * HD;
            const __half* wh = sW4 + h * HD * HD;
#pragma unroll
            for (int kk = 0; kk < 4; kk++) {
                wmma::load_matrix_sync(af, arow + kk * 16, HD);
#pragma unroll
                for (int nn = 0; nn < 4; nn++) {
                    wmma::load_matrix_sync(bf, wh + kk * 16 * HD + nn * 16, HD);
                    wmma::mma_sync(acc[nn], af, bf, acc[nn]);
                }
            }
        }
#pragma unroll
        for (int nn = 0; nn < 4; nn++)
            wmma::store_matrix_sync(sOut + nn * 16, acc[nn], T2_LD, wmma::mem_row_major);
        __syncwarp();
        for (int idx = lane; idx < 16 * HD; idx += 32) {
            int n = idx >> 6, j = idx & 63;
            sOut[n * T2_LD + j] = fmaxf(sOut[n * T2_LD + j] + sB[j], 0.f);
        }
        __syncwarp();
#pragma unroll
        for (int pass = 0; pass < 4; pass++) {
            int n = pass * 4 + (lane >> 3);
            int o = lane & 7;
            float a = sLB[o];
            const float* s3 = sOut + n * T2_LD;
#pragma unroll 8
            for (int k = 0; k < HD; k++) a = fmaf(s3[k], sLW[k * OD + o], a);
            out[(size_t)(t * 16 + n) * OD + o] = a;
        }
        __syncwarp();
    }
}

// ---------------- host orchestration ------------------------------------------
extern "C" void kernel_launch(void* const* d_in, const int* in_sizes, int n_in,
                              void* d_out, int out_size) {
    const float* x_game  = (const float*)d_in[0];
    const float* x_state = (const float*)d_in[1];
    const void*  e_gg = d_in[2];
    const void*  e_h  = d_in[3];
    const void*  e_in = d_in[4];
    const void*  e_ss = d_in[5];
    const float* ew       = (const float*)d_in[6];
    const float* tag1_w   = (const float*)d_in[7];
    const float* tag1_b   = (const float*)d_in[8];
    const float* tag2_w   = (const float*)d_in[9];
    const float* tag2_b   = (const float*)d_in[10];
    const float* gc_w_rel = (const float*)d_in[11];
    const float* gc_b_rel = (const float*)d_in[12];
    const float* gc_w_root= (const float*)d_in[13];
    const float* sage_w_l = (const float*)d_in[14];
    const float* sage_b_l = (const float*)d_in[15];
    const float* sage_w_r = (const float*)d_in[16];
    const float* lin_w    = (const float*)d_in[17];
    const float* lin_b    = (const float*)d_in[18];

    int Egg = in_sizes[2] / 2; if (Egg > EGGMAX) Egg = EGGMAX;
    int Eh  = in_sizes[3] / 2; if (Eh  > EHMAX)  Eh  = EHMAX;
    int Ein = in_sizes[4] / 2; if (Ein > EINMAX) Ein = EINMAX;
    int Ess = in_sizes[5] / 2; if (Ess > ESSMAX) Ess = ESSMAX;

    int *p_hgg, *p_hh, *p_hin, *p_hss;
    int *p_rgg, *p_rh, *p_rin, *p_rss;
    int *p_cur0, *p_cur1, *p_cur2, *p_cur3;
    int *p_b0, *p_b1, *p_b2, *p_b3;
    int *p_sgg, *p_sh, *p_sin;
    int2 *p_css;
    float *p_wgg, *p_wh;
    float *p_dinv1, *p_dinv2;
    __half *p_xg16, *p_x1h, *p_x2h, *p_gamex16, *p_agg1h, *p_agg2h;
    __half *p_state2h, *p_h1h, *p_h2h, *p_h3h;
    cudaGetSymbolAddress((void**)&p_hgg, g_hist_gg);
    cudaGetSymbolAddress((void**)&p_hh,  g_hist_h);
    cudaGetSymbolAddress((void**)&p_hin, g_hist_in);
    cudaGetSymbolAddress((void**)&p_hss, g_hist_ss);
    cudaGetSymbolAddress((void**)&p_rgg, g_rp_gg);
    cudaGetSymbolAddress((void**)&p_rh,  g_rp_h);
    cudaGetSymbolAddress((void**)&p_rin, g_rp_in);
    cudaGetSymbolAddress((void**)&p_rss, g_rp_ss);
    cudaGetSymbolAddress((void**)&p_cur0, g_cur0);
    cudaGetSymbolAddress((void**)&p_cur1, g_cur1);
    cudaGetSymbolAddress((void**)&p_cur2, g_cur2);
    cudaGetSymbolAddress((void**)&p_cur3, g_cur3);
    cudaGetSymbolAddress((void**)&p_b0, g_bsum0);
    cudaGetSymbolAddress((void**)&p_b1, g_bsum1);
    cudaGetSymbolAddress((void**)&p_b2, g_bsum2);
    cudaGetSymbolAddress((void**)&p_b3, g_bsum3);
    cudaGetSymbolAddress((void**)&p_sgg, g_src_gg);
    cudaGetSymbolAddress((void**)&p_sh,  g_src_h);
    cudaGetSymbolAddress((void**)&p_sin, g_src_in);
    cudaGetSymbolAddress((void**)&p_css, g_csr_ss);
    cudaGetSymbolAddress((void**)&p_wgg, g_w_gg);
    cudaGetSymbolAddress((void**)&p_wh,  g_w_h);
    cudaGetSymbolAddress((void**)&p_dinv1, g_dinv1);
    cudaGetSymbolAddress((void**)&p_dinv2, g_dinv2);
    cudaGetSymbolAddress((void**)&p_xg16, g_xg16);
    cudaGetSymbolAddress((void**)&p_x1h,  g_x1h);
    cudaGetSymbolAddress((void**)&p_x2h,  g_x2h);
    cudaGetSymbolAddress((void**)&p_gamex16, g_gamex16);
    cudaGetSymbolAddress((void**)&p_agg1h, g_agg1h);
    cudaGetSymbolAddress((void**)&p_agg2h, g_agg2h);
    cudaGetSymbolAddress((void**)&p_state2h, g_state2h);
    cudaGetSymbolAddress((void**)&p_h1h, g_h1h);
    cudaGetSymbolAddress((void**)&p_h2h, g_h2h);
    cudaGetSymbolAddress((void**)&p_h3h, g_h3h);

    static cudaStream_t s1, s2, s3;
    static cudaEvent_t evFork, evGX, evAGG2, evSAGE, evSS;
    static bool init_done = false;
    if (!init_done) {
        cudaStreamCreateWithFlags(&s1, cudaStreamNonBlocking);
        cudaStreamCreateWithFlags(&s2, cudaStreamNonBlocking);
        cudaStreamCreateWithFlags(&s3, cudaStreamNonBlocking);
        cudaEventCreateWithFlags(&evFork, cudaEventDisableTiming);
        cudaEventCreateWithFlags(&evGX,   cudaEventDisableTiming);
        cudaEventCreateWithFlags(&evAGG2, cudaEventDisableTiming);
        cudaEventCreateWithFlags(&evSAGE, cudaEventDisableTiming);
        cudaEventCreateWithFlags(&evSS,   cudaEventDisableTiming);
        cudaFuncSetAttribute(k_sage_w, cudaFuncAttributeMaxDynamicSharedMemorySize,
                             SAGE_SMEM);
        cudaFuncSetAttribute(k_tag2f_w, cudaFuncAttributeMaxDynamicSharedMemorySize,
                             T2F_SMEM);
        init_done = true;
    }

    const int TB = 256;
    #define NB(n) (((n) + TB - 1) / TB)

    // ---- root: hoisted gg-hist memset (no deps), dtype detect + pack5 ----
    cudaMemsetAsync(p_hgg, 0, (size_t)NN * 4, 0);
    k_detect<<<1, 4>>>((const unsigned*)e_gg, (const unsigned*)e_h,
                       (const unsigned*)e_in, (const unsigned*)e_ss);
    k_pack5<<<NN / TB, TB>>>(x_game, p_xg16);
    cudaEventRecord(evFork, 0);
    cudaStreamWaitEvent(s1, evFork, 0);
    cudaStreamWaitEvent(s2, evFork, 0);
    cudaStreamWaitEvent(s3, evFork, 0);

    // ---- s1: hist-edge CSR ----
    cudaMemsetAsync(p_hh, 0, (size_t)NN * 4, s1);
    k_hist<<<NB(Eh), TB, 0, s1>>>(e_h, Eh, 1, p_hh);
    k_scan1d<<<512, 512, 0, s1>>>(p_hh, p_rh, p_b1, nullptr);
    k_scan23<<<512, 512, 0, s1>>>(p_rh, p_cur1, p_b1, Eh);
    k_place<1><<<NB(Eh), TB, 0, s1>>>(e_h, Eh, 1, p_cur1, p_sh, p_wh, nullptr, ew);

    // ---- s2: tag2 weight conversion + in-edge CSR ----
    k_cvtw<<<64, 256, 0, s2>>>(tag2_w);
    cudaMemsetAsync(p_hin, 0, (size_t)NN * 4, s2);
    k_hist<<<NB(Ein), TB, 0, s2>>>(e_in, Ein, 2, p_hin);
    k_scan1d<<<512, 512, 0, s2>>>(p_hin, p_rin, p_b2, nullptr);
    k_scan23<<<512, 512, 0, s2>>>(p_rin, p_cur2, p_b2, Ein);
    k_place<2><<<NB(Ein), TB, 0, s2>>>(e_in, Ein, 2, p_cur2, p_sin, nullptr, nullptr, nullptr);

    // ---- s3: ss-edge CSR (packed int2) ----
    cudaMemsetAsync(p_hss, 0, (size_t)NN * 4, s3);
    k_hist<<<NB(Ess), TB, 0, s3>>>(e_ss, Ess, 3, p_hss);
    k_scan1d<<<512, 512, 0, s3>>>(p_hss, p_rss, p_b3, p_dinv2);
    k_scan23<<<512, 512, 0, s3>>>(p_rss, p_cur3, p_b3, Ess);
    k_place_ss<<<NB(Ess), TB, 0, s3>>>(e_ss, Ess, 3, p_cur3, p_css, p_dinv2);
    cudaEventRecord(evSS, s3);

    // ---- s0: gg CSR + TAGConv1 -> gamex fp16 ----
    k_hist<<<NB(Egg), TB>>>(e_gg, Egg, 0, p_hgg);
    k_scan1d<<<512, 512>>>(p_hgg, p_rgg, p_b0, p_dinv1);
    k_scan23<<<512, 512>>>(p_rgg, p_cur0, p_b0, Egg);
    k_place<0><<<NB(Egg), TB>>>(e_gg, Egg, 0, p_cur0, p_sgg, p_wgg, p_dinv1, nullptr);
    k_pull5<<<NN * 8 / TB, TB>>>(p_rgg, p_sgg, p_wgg, p_dinv1, p_xg16, p_x1h);
    k_pull5<<<NN * 8 / TB, TB>>>(p_rgg, p_sgg, p_wgg, p_dinv1, p_x1h, p_x2h);
    k_tag1_p<<<2048, TB>>>(x_game, tag1_w, tag1_b);
    cudaEventRecord(evGX, 0);

    // ---- s1: GraphConv path (needs gamex + h CSR) ----
    cudaStreamWaitEvent(s1, evGX, 0);
    k_pull64<1><<<NN * 16 / TB, TB, 0, s1>>>(p_rh, p_sh, p_wh, nullptr,
                                             p_gamex16, p_agg1h);
    k_gc_w<<<512, TB, 0, s1>>>(x_state, gc_w_rel, gc_b_rel, gc_w_root);

    // ---- s2: SAGE aggregation (needs gamex + in CSR) ----
    cudaStreamWaitEvent(s2, evGX, 0);
    k_pull64<2><<<NN * 16 / TB, TB, 0, s2>>>(p_rin, p_sin, nullptr, nullptr,
                                             p_gamex16, p_agg2h);
    cudaEventRecord(evAGG2, s2);

    // ---- s1: SAGE combine -> state2 fp16 ----
    cudaStreamWaitEvent(s1, evAGG2, 0);
    k_sage_w<<<592, TB, SAGE_SMEM, s1>>>(sage_w_l, sage_b_l, sage_w_r);
    cudaEventRecord(evSAGE, s1);

    // ---- s0: TAGConv2 (needs state2 + ss CSR, packed) + fused final ----
    cudaStreamWaitEvent(0, evSAGE, 0);
    cudaStreamWaitEvent(0, evSS, 0);
    k_pull64_ss<<<NN * 16 / TB, TB>>>(p_rss, p_css, p_dinv2, p_state2h, p_h1h);
    k_pull64_ss<<<NN * 16 / TB, TB>>>(p_rss, p_css, p_dinv2, p_h1h, p_h2h);
    k_pull64_ss<<<NN * 16 / TB, TB>>>(p_rss, p_css, p_dinv2, p_h2h, p_h3h);
    k_tag2f_w<<<444, TB, T2F_SMEM>>>(tag2_b, lin_w, lin_b, (float*)d_out);
    #undef NB
}

// round 15
// speedup vs baseline: 1.0483x; 1.0483x over previous
#include <cuda_runtime.h>
#include <cuda_fp16.h>
#include <mma.h>
#include <math.h>

using namespace nvcuda;

#define NN   262144
#define HD   64
#define DGI  5
#define DSI  6
#define OD   8
#define EGGMAX 4000000
#define EHMAX  2000000
#define EINMAX 2000000
#define ESSMAX 2000000
#define NGROUPS (NN / 4)
#define NTILES (NN / 16)

// ---------------- scratch (device globals; no allocs) -------------------------
__device__ int   g_is64[4];
__device__ int   g_hist_gg[NN], g_hist_h[NN], g_hist_in[NN], g_hist_ss[NN];
__device__ int   g_rp_gg[NN+1], g_rp_h[NN+1], g_rp_in[NN+1], g_rp_ss[NN+1];
__device__ int   g_cur0[NN], g_cur1[NN], g_cur2[NN], g_cur3[NN];
__device__ int   g_bsum0[512], g_bsum1[512], g_bsum2[512], g_bsum3[512];
__device__ int   g_src_gg[EGGMAX];  __device__ float g_w_gg[EGGMAX];
__device__ int   g_src_h [EHMAX];   __device__ float g_w_h [EHMAX];
__device__ int   g_src_in[EINMAX];
__device__ int   g_src_ss[ESSMAX];  __device__ float g_w_ss[ESSMAX];
__device__ float g_dinv1[NN], g_dinv2[NN];
// fp16 feature arrays
__device__ __half g_xg16[NN*8];
__device__ __half g_x1h[NN*8], g_x2h[NN*8];
__device__ __half g_gamex16[NN*HD];
__device__ __half g_agg1h[NN*HD];
__device__ __half g_agg2h[NN*HD];
__device__ __half g_state1h[NN*HD];
__device__ __half g_state2h[NN*HD];
__device__ __half g_h1h[NN*HD], g_h2h[NN*HD], g_h3h[NN*HD];
// pre-converted fp16 tag2 weights
__device__ __half g_tw16[4*HD*HD];

// ---------------- dtype detection ---------------------------------------------
__global__ void k_detect(const unsigned* a0, const unsigned* a1,
                         const unsigned* a2, const unsigned* a3) {
    const unsigned* arr[4] = {a0, a1, a2, a3};
    int i = threadIdx.x;
    if (i < 4) {
        const unsigned* p = arr[i];
        int ok = 1;
        for (int k = 0; k < 64; k++) if (p[2*k+1] != 0u) { ok = 0; break; }
        g_is64[i] = ok;
    }
}

__device__ __forceinline__ int fetch_col(const void* p, int E, int is64, int e) {
    if (is64) return (int)((const long long*)p)[(long)E + e];
    return ((const int*)p)[E + e];
}
__device__ __forceinline__ int fetch_row(const void* p, int E, int is64, int e) {
    if (is64) return (int)((const long long*)p)[e];
    return ((const int*)p)[e];
}

// ---------------- CSR build ---------------------------------------------------
__global__ void k_hist(const void* p, int E, int flag, int* __restrict__ hist) {
    int e = blockIdx.x * blockDim.x + threadIdx.x;
    if (e >= E) return;
    int is64 = g_is64[flag];
    atomicAdd(&hist[fetch_col(p, E, is64, e)], 1);
}

// scan1 fused with dinv (optional): dinv[i] = rsqrt(hist[i]) while scanning
__global__ void k_scan1d(const int* __restrict__ hist, int* __restrict__ rp,
                         int* __restrict__ bsum, float* __restrict__ dinv) {
    __shared__ int sh[512];
    int t = threadIdx.x;
    int i = blockIdx.x * 512 + t;
    int v = hist[i];
    if (dinv) dinv[i] = v > 0 ? rsqrtf((float)v) : 0.f;
    sh[t] = v; __syncthreads();
    for (int o = 1; o < 512; o <<= 1) {
        int tmp = (t >= o) ? sh[t - o] : 0;
        __syncthreads();
        sh[t] += tmp;
        __syncthreads();
    }
    rp[i] = sh[t] - v;
    if (t == 511) bsum[blockIdx.x] = sh[511];
}

// fused: every block redundantly scans block-sums, adds offset, writes cursor
__global__ void k_scan23(int* __restrict__ rp, int* __restrict__ cur,
                         const int* __restrict__ bsum, int E) {
    __shared__ int sh[512];
    int t = threadIdx.x;
    sh[t] = bsum[t];
    __syncthreads();
    for (int o = 1; o < 512; o <<= 1) {
        int tmp = (t >= o) ? sh[t - o] : 0;
        __syncthreads();
        sh[t] += tmp;
        __syncthreads();
    }
    int add = (blockIdx.x > 0) ? sh[blockIdx.x - 1] : 0;
    int i = blockIdx.x * 512 + t;
    int v = rp[i] + add;
    rp[i] = v;
    cur[i] = v;
    if (i == NN - 1) rp[NN] = E;
}

template<int WMODE>
__global__ void k_place(const void* p, int E, int flag, int* __restrict__ cursor,
                        int* __restrict__ csr_src, float* __restrict__ csr_w,
                        const float* __restrict__ dinv, const float* __restrict__ ew) {
    int e = blockIdx.x * blockDim.x + threadIdx.x;
    if (e >= E) return;
    int is64 = g_is64[flag];
    int r = fetch_row(p, E, is64, e);
    int c = fetch_col(p, E, is64, e);
    int pos = atomicAdd(&cursor[c], 1);
    csr_src[pos] = r;
    if (WMODE == 0) csr_w[pos] = dinv[r];
    if (WMODE == 1) csr_w[pos] = ew[e];
}

// ---------------- weight preconversion + pack5 --------------------------------
__global__ void k_cvtw(const float* __restrict__ w) {
    int i = blockIdx.x * blockDim.x + threadIdx.x;
    g_tw16[i] = __float2half(w[i]);
}

__global__ void k_pack5(const float* __restrict__ x, __half* __restrict__ o) {
    int i = blockIdx.x * blockDim.x + threadIdx.x;
    if (i >= NN) return;
    const float* r = x + (long)i * DGI;
    __half h[8];
#pragma unroll
    for (int k = 0; k < 5; k++) h[k] = __float2half(r[k]);
    h[5] = h[6] = h[7] = __float2half(0.f);
    ((uint4*)o)[i] = *(uint4*)h;
}

// ---------------- pull: dim-5 TAG hop (8 lanes/node, 2-edge unroll) -----------
__global__ void k_pull5(const int* __restrict__ rp, const int* __restrict__ csr_src,
                        const float* __restrict__ csr_w, const float* __restrict__ dinv,
                        const __half* __restrict__ xin, __half* __restrict__ xout) {
    int tid = blockIdx.x * blockDim.x + threadIdx.x;
    int node = tid >> 3, sub = tid & 7;
    int s = rp[node], e = rp[node + 1];
    float a0 = 0, a1 = 0, a2 = 0, a3 = 0, a4 = 0;
    int i = s + sub;
    for (; i + 8 < e; i += 16) {
        int r0 = csr_src[i], r1 = csr_src[i + 8];
        float w0 = csr_w[i], w1 = csr_w[i + 8];
        uint4 u0 = ((const uint4*)xin)[r0];
        uint4 u1 = ((const uint4*)xin)[r1];
        __half2* hp0 = (__half2*)&u0;
        __half2* hp1 = (__half2*)&u1;
        float2 p00 = __half22float2(hp0[0]), p01 = __half22float2(hp0[1]);
        float2 p02 = __half22float2(hp0[2]);
        float2 p10 = __half22float2(hp1[0]), p11 = __half22float2(hp1[1]);
        float2 p12 = __half22float2(hp1[2]);
        a0 = fmaf(w0, p00.x, a0); a1 = fmaf(w0, p00.y, a1);
        a2 = fmaf(w0, p01.x, a2); a3 = fmaf(w0, p01.y, a3);
        a4 = fmaf(w0, p02.x, a4);
        a0 = fmaf(w1, p10.x, a0); a1 = fmaf(w1, p10.y, a1);
        a2 = fmaf(w1, p11.x, a2); a3 = fmaf(w1, p11.y, a3);
        a4 = fmaf(w1, p12.x, a4);
    }
    if (i < e) {
        int r = csr_src[i];
        float w = csr_w[i];
        uint4 u = ((const uint4*)xin)[r];
        __half2* hp = (__half2*)&u;
        float2 p0 = __half22float2(hp[0]);
        float2 p1 = __half22float2(hp[1]);
        float2 p2 = __half22float2(hp[2]);
        a0 = fmaf(w, p0.x, a0); a1 = fmaf(w, p0.y, a1);
        a2 = fmaf(w, p1.x, a2); a3 = fmaf(w, p1.y, a3);
        a4 = fmaf(w, p2.x, a4);
    }
#pragma unroll
    for (int o = 4; o; o >>= 1) {
        a0 += __shfl_down_sync(0xffffffffu, a0, o, 8);
        a1 += __shfl_down_sync(0xffffffffu, a1, o, 8);
        a2 += __shfl_down_sync(0xffffffffu, a2, o, 8);
        a3 += __shfl_down_sync(0xffffffffu, a3, o, 8);
        a4 += __shfl_down_sync(0xffffffffu, a4, o, 8);
    }
    if (sub == 0) {
        float dc = dinv[node];
        __half h[8];
        h[0] = __float2half(dc * a0); h[1] = __float2half(dc * a1);
        h[2] = __float2half(dc * a2); h[3] = __float2half(dc * a3);
        h[4] = __float2half(dc * a4);
        h[5] = h[6] = h[7] = __float2half(0.f);
        ((uint4*)xout)[node] = *(uint4*)h;
    }
}

// ---------------- pull: dim-64 hop (16 lanes/node; 2×8-lane halves, uint4) ----
// Each 16-lane group owns one node. Lanes split into two 8-lane halves that
// process even/odd edges with LDG.128 row reads; halves merged via shfl_xor(8).
// MODE 0: weighted + dinv scale (TAG); 1: weighted (GC); 2: mean (SAGE)
template<int MODE>
__global__ void __launch_bounds__(256)
k_pull64(const int* __restrict__ rp, const int* __restrict__ csr_src,
         const float* __restrict__ csr_w, const float* __restrict__ dinv,
         const __half* __restrict__ xin, __half* __restrict__ xout) {
    int gtid = blockIdx.x * blockDim.x + threadIdx.x;
    int node = gtid >> 4;
    int sub = threadIdx.x & 15;
    int half = sub >> 3;
    int l8 = sub & 7;
    int s = rp[node], e = rp[node + 1];
    float a[8];
#pragma unroll
    for (int q = 0; q < 8; q++) a[q] = 0.f;
    int i = s + half;
    for (; i + 2 < e; i += 4) {
        int r0 = csr_src[i], r1 = csr_src[i + 2];
        uint4 u0 = ((const uint4*)(xin + (size_t)r0 * HD))[l8];
        uint4 u1 = ((const uint4*)(xin + (size_t)r1 * HD))[l8];
        __half2* h0 = (__half2*)&u0;
        __half2* h1 = (__half2*)&u1;
        if (MODE == 2) {
#pragma unroll
            for (int q = 0; q < 4; q++) {
                float2 f0 = __half22float2(h0[q]);
                float2 f1 = __half22float2(h1[q]);
                a[2*q]     += f0.x + f1.x;
                a[2*q + 1] += f0.y + f1.y;
            }
        } else {
            float w0 = csr_w[i], w1 = csr_w[i + 2];
#pragma unroll
            for (int q = 0; q < 4; q++) {
                float2 f0 = __half22float2(h0[q]);
                float2 f1 = __half22float2(h1[q]);
                a[2*q]     = fmaf(w0, f0.x, a[2*q]);
                a[2*q + 1] = fmaf(w0, f0.y, a[2*q + 1]);
                a[2*q]     = fmaf(w1, f1.x, a[2*q]);
                a[2*q + 1] = fmaf(w1, f1.y, a[2*q + 1]);
            }
        }
    }
    for (; i < e; i += 2) {
        int r0 = csr_src[i];
        uint4 u0 = ((const uint4*)(xin + (size_t)r0 * HD))[l8];
        __half2* h0 = (__half2*)&u0;
        if (MODE == 2) {
#pragma unroll
            for (int q = 0; q < 4; q++) {
                float2 f0 = __half22float2(h0[q]);
                a[2*q] += f0.x; a[2*q + 1] += f0.y;
            }
        } else {
            float w0 = csr_w[i];
#pragma unroll
            for (int q = 0; q < 4; q++) {
                float2 f0 = __half22float2(h0[q]);
                a[2*q]     = fmaf(w0, f0.x, a[2*q]);
                a[2*q + 1] = fmaf(w0, f0.y, a[2*q + 1]);
            }
        }
    }
    // merge even/odd halves (xor 8 stays within each 16-lane group)
#pragma unroll
    for (int q = 0; q < 8; q++)
        a[q] += __shfl_xor_sync(0xffffffffu, a[q], 8);
    if (MODE == 0) {
        float d = dinv[node];
#pragma unroll
        for (int q = 0; q < 8; q++) a[q] *= d;
    }
    if (MODE == 2) {
        int c = e - s;
        if (c > 0) {
            float inv = 1.f / (float)c;
#pragma unroll
            for (int q = 0; q < 8; q++) a[q] *= inv;
        }
    }
    if (half == 0) {
        __half hout[8];
#pragma unroll
        for (int q = 0; q < 8; q++) hout[q] = __float2half(a[q]);
        ((uint4*)(xout + (size_t)node * HD))[l8] = *(uint4*)hout;
    }
}

// ---------------- TAG1 combine (persistent scalar; tiny K) --------------------
__global__ void k_tag1_p(const float* __restrict__ xg, const float* __restrict__ w,
                         const float* __restrict__ b) {
    __shared__ float sW[3 * DGI * HD];
    __shared__ float sB[HD];
    int tid = threadIdx.x;
    for (int i = tid; i < 3 * DGI * HD; i += 256) sW[i] = w[i];
    if (tid < HD) sB[tid] = b[tid];
    __syncthreads();
    int nl = tid >> 6, j = tid & 63;
    for (int g = blockIdx.x; g < NGROUPS; g += gridDim.x) {
        int node = g * 4 + nl;
        float acc = sB[j];
        const float* x0 = xg + (long)node * DGI;
        uint4 u1 = ((const uint4*)g_x1h)[node];
        uint4 u2 = ((const uint4*)g_x2h)[node];
        __half* h1 = (__half*)&u1;
        __half* h2 = (__half*)&u2;
#pragma unroll
        for (int k = 0; k < DGI; k++) {
            acc = fmaf(x0[k],               sW[k * HD + j],             acc);
            acc = fmaf(__half2float(h1[k]), sW[(DGI + k) * HD + j],     acc);
            acc = fmaf(__half2float(h2[k]), sW[(2 * DGI + k) * HD + j], acc);
        }
        g_gamex16[(size_t)node * HD + j] = __float2half(fmaxf(acc, 0.f));
    }
}

// ---------------- GraphConv combine (wmma) ------------------------------------
__global__ void k_gc_w(const float* __restrict__ xs, const float* __restrict__ wrel,
                       const float* __restrict__ brel, const float* __restrict__ wroot) {
    __shared__ __half sWh[HD * HD];
    __shared__ float sWroot[DSI * HD];
    __shared__ float sB[HD];
    __shared__ float sOut[8][16 * HD];
    __shared__ float sXr[8][16 * DSI];
    int tid = threadIdx.x;
    int wid = tid >> 5, lane = tid & 31;
    for (int i = tid; i < HD * HD; i += 256) sWh[i] = __float2half(wrel[i]);
    for (int i = tid; i < DSI * HD; i += 256) sWroot[i] = wroot[i];
    if (tid < HD) sB[tid] = brel[tid];
    __syncthreads();

    wmma::fragment<wmma::matrix_b, 16, 16, 16, __half, wmma::row_major> bf;
    wmma::fragment<wmma::matrix_a, 16, 16, 16, __half, wmma::row_major> af;
    wmma::fragment<wmma::accumulator, 16, 16, 16, float> acc[4];

    for (int t = blockIdx.x * 8 + wid; t < NTILES; t += gridDim.x * 8) {
        const __half* arow = g_agg1h + (size_t)t * 16 * HD;
#pragma unroll
        for (int nn = 0; nn < 4; nn++) wmma::fill_fragment(acc[nn], 0.f);
#pragma unroll
        for (int kk = 0; kk < 4; kk++) {
            wmma::load_matrix_sync(af, arow + kk * 16, HD);
#pragma unroll
            for (int nn = 0; nn < 4; nn++) {
                wmma::load_matrix_sync(bf, sWh + kk * 16 * HD + nn * 16, HD);
                wmma::mma_sync(acc[nn], af, bf, acc[nn]);
            }
        }
#pragma unroll
        for (int nn = 0; nn < 4; nn++)
            wmma::store_matrix_sync(&sOut[wid][nn * 16], acc[nn], HD, wmma::mem_row_major);
        for (int i = lane; i < 16 * DSI; i += 32)
            sXr[wid][i] = xs[(size_t)t * 16 * DSI + i];
        __syncwarp();
        for (int idx = lane; idx < 16 * HD; idx += 32) {
            int n = idx >> 6, j = idx & 63;
            float v = sOut[wid][idx] + sB[j];
#pragma unroll
            for (int k = 0; k < DSI; k++)
                v = fmaf(sXr[wid][n * DSI + k], sWroot[k * HD + j], v);
            g_state1h[(size_t)t * 16 * HD + idx] = __float2half(fmaxf(v, 0.f));
        }
        __syncwarp();
    }
}

// ---------------- SAGE combine (wmma, dynamic smem) ---------------------------
#define SAGE_SMEM (HD*HD*2*2 + HD*4 + 8*16*HD*4)
__global__ void k_sage_w(const float* __restrict__ wl, const float* __restrict__ bl,
                         const float* __restrict__ wr) {
    extern __shared__ char dyn[];
    __half* sWl = (__half*)dyn;
    __half* sWr = sWl + HD * HD;
    float* sB   = (float*)(sWr + HD * HD);
    float* sOutBase = sB + HD;
    int tid = threadIdx.x;
    int wid = tid >> 5, lane = tid & 31;
    float* sOut = sOutBase + wid * 16 * HD;
    for (int i = tid; i < HD * HD; i += 256) {
        sWl[i] = __float2half(wl[i]);
        sWr[i] = __float2half(wr[i]);
    }
    if (tid < HD) sB[tid] = bl[tid];
    __syncthreads();

    wmma::fragment<wmma::matrix_b, 16, 16, 16, __half, wmma::row_major> bf;
    wmma::fragment<wmma::matrix_a, 16, 16, 16, __half, wmma::row_major> af;
    wmma::fragment<wmma::accumulator, 16, 16, 16, float> acc[4];

    for (int t = blockIdx.x * 8 + wid; t < NTILES; t += gridDim.x * 8) {
#pragma unroll
        for (int nn = 0; nn < 4; nn++) wmma::fill_fragment(acc[nn], 0.f);
        const __half* a0 = g_agg2h   + (size_t)t * 16 * HD;
        const __half* a1 = g_state1h + (size_t)t * 16 * HD;
#pragma unroll
        for (int kk = 0; kk < 4; kk++) {
            wmma::load_matrix_sync(af, a0 + kk * 16, HD);
#pragma unroll
            for (int nn = 0; nn < 4; nn++) {
                wmma::load_matrix_sync(bf, sWl + kk * 16 * HD + nn * 16, HD);
                wmma::mma_sync(acc[nn], af, bf, acc[nn]);
            }
        }
#pragma unroll
        for (int kk = 0; kk < 4; kk++) {
            wmma::load_matrix_sync(af, a1 + kk * 16, HD);
#pragma unroll
            for (int nn = 0; nn < 4; nn++) {
                wmma::load_matrix_sync(bf, sWr + kk * 16 * HD + nn * 16, HD);
                wmma::mma_sync(acc[nn], af, bf, acc[nn]);
            }
        }
#pragma unroll
        for (int nn = 0; nn < 4; nn++)
            wmma::store_matrix_sync(sOut + nn * 16, acc[nn], HD, wmma::mem_row_major);
        __syncwarp();
        for (int idx = lane; idx < 16 * HD; idx += 32) {
            int j = idx & 63;
            float v = sOut[idx] + sB[j];
            g_state2h[(size_t)t * 16 * HD + idx] = __float2half(fmaxf(v, 0.f));
        }
        __syncwarp();
    }
}

// ---------------- TAG2 combine + final linear (wmma, dynamic smem) ------------
#define T2_LD 68
#define T2F_SMEM (4*HD*HD*2 + HD*OD*4 + HD*4 + OD*4 + 8*16*T2_LD*4)
__global__ void k_tag2f_w(const float* __restrict__ b,
                          const float* __restrict__ lw, const float* __restrict__ lb,
                          float* __restrict__ out) {
    extern __shared__ char dyn[];
    __half* sW4 = (__half*)dyn;
    float* sLW = (float*)(sW4 + 4 * HD * HD);
    float* sB  = sLW + HD * OD;
    float* sLB = sB + HD;
    float* sOutBase = sLB + OD;
    int tid = threadIdx.x;
    int wid = tid >> 5, lane = tid & 31;
    float* sOut = sOutBase + wid * 16 * T2_LD;
    // fp16 weights pre-converted by k_cvtw -> bulk uint4 copy
    for (int i = tid; i < 4 * HD * HD / 8; i += 256)
        ((uint4*)sW4)[i] = ((const uint4*)g_tw16)[i];
    for (int i = tid; i < HD * OD; i += 256) sLW[i] = lw[i];
    if (tid < HD) sB[tid] = b[tid];
    if (tid < OD) sLB[tid] = lb[tid];
    __syncthreads();

    wmma::fragment<wmma::matrix_b, 16, 16, 16, __half, wmma::row_major> bf;
    wmma::fragment<wmma::matrix_a, 16, 16, 16, __half, wmma::row_major> af;
    wmma::fragment<wmma::accumulator, 16, 16, 16, float> acc[4];
    const __half* srcs[4] = {g_state2h, g_h1h, g_h2h, g_h3h};

    for (int t = blockIdx.x * 8 + wid; t < NTILES; t += gridDim.x * 8) {
#pragma unroll
        for (int nn = 0; nn < 4; nn++) wmma::fill_fragment(acc[nn], 0.f);
#pragma unroll
        for (int h = 0; h < 4; h++) {
            const __half* arow = srcs[h] + (size_t)t * 16 * HD;
            const __half* wh = sW4 + h * HD * HD;
#pragma unroll
            for (int kk = 0; kk < 4; kk++) {
                wmma::load_matrix_sync(af, arow + kk * 16, HD);
#pragma unroll
                for (int nn = 0; nn < 4; nn++) {
                    wmma::load_matrix_sync(bf, wh + kk * 16 * HD + nn * 16, HD);
                    wmma::mma_sync(acc[nn], af, bf, acc[nn]);
                }
            }
        }
#pragma unroll
        for (int nn = 0; nn < 4; nn++)
            wmma::store_matrix_sync(sOut + nn * 16, acc[nn], T2_LD, wmma::mem_row_major);
        __syncwarp();
        for (int idx = lane; idx < 16 * HD; idx += 32) {
            int n = idx >> 6, j = idx & 63;
            sOut[n * T2_LD + j] = fmaxf(sOut[n * T2_LD + j] + sB[j], 0.f);
        }
        __syncwarp();
#pragma unroll
        for (int pass = 0; pass < 4; pass++) {
            int n = pass * 4 + (lane >> 3);
            int o = lane & 7;
            float a = sLB[o];
            const float* s3 = sOut + n * T2_LD;
#pragma unroll 8
            for (int k = 0; k < HD; k++) a = fmaf(s3[k], sLW[k * OD + o], a);
            out[(size_t)(t * 16 + n) * OD + o] = a;
        }
        __syncwarp();
    }
}

// ---------------- host orchestration ------------------------------------------
extern "C" void kernel_launch(void* const* d_in, const int* in_sizes, int n_in,
                              void* d_out, int out_size) {
    const float* x_game  = (const float*)d_in[0];
    const float* x_state = (const float*)d_in[1];
    const void*  e_gg = d_in[2];
    const void*  e_h  = d_in[3];
    const void*  e_in = d_in[4];
    const void*  e_ss = d_in[5];
    const float* ew       = (const float*)d_in[6];
    const float* tag1_w   = (const float*)d_in[7];
    const float* tag1_b   = (const float*)d_in[8];
    const float* tag2_w   = (const float*)d_in[9];
    const float* tag2_b   = (const float*)d_in[10];
    const float* gc_w_rel = (const float*)d_in[11];
    const float* gc_b_rel = (const float*)d_in[12];
    const float* gc_w_root= (const float*)d_in[13];
    const float* sage_w_l = (const float*)d_in[14];
    const float* sage_b_l = (const float*)d_in[15];
    const float* sage_w_r = (const float*)d_in[16];
    const float* lin_w    = (const float*)d_in[17];
    const float* lin_b    = (const float*)d_in[18];

    int Egg = in_sizes[2] / 2; if (Egg > EGGMAX) Egg = EGGMAX;
    int Eh  = in_sizes[3] / 2; if (Eh  > EHMAX)  Eh  = EHMAX;
    int Ein = in_sizes[4] / 2; if (Ein > EINMAX) Ein = EINMAX;
    int Ess = in_sizes[5] / 2; if (Ess > ESSMAX) Ess = ESSMAX;

    int *p_hgg, *p_hh, *p_hin, *p_hss;
    int *p_rgg, *p_rh, *p_rin, *p_rss;
    int *p_cur0, *p_cur1, *p_cur2, *p_cur3;
    int *p_b0, *p_b1, *p_b2, *p_b3;
    int *p_sgg, *p_sh, *p_sin, *p_sss;
    float *p_wgg, *p_wh, *p_wss;
    float *p_dinv1, *p_dinv2;
    __half *p_xg16, *p_x1h, *p_x2h, *p_gamex16, *p_agg1h, *p_agg2h;
    __half *p_state2h, *p_h1h, *p_h2h, *p_h3h;
    cudaGetSymbolAddress((void**)&p_hgg, g_hist_gg);
    cudaGetSymbolAddress((void**)&p_hh,  g_hist_h);
    cudaGetSymbolAddress((void**)&p_hin, g_hist_in);
    cudaGetSymbolAddress((void**)&p_hss, g_hist_ss);
    cudaGetSymbolAddress((void**)&p_rgg, g_rp_gg);
    cudaGetSymbolAddress((void**)&p_rh,  g_rp_h);
    cudaGetSymbolAddress((void**)&p_rin, g_rp_in);
    cudaGetSymbolAddress((void**)&p_rss, g_rp_ss);
    cudaGetSymbolAddress((void**)&p_cur0, g_cur0);
    cudaGetSymbolAddress((void**)&p_cur1, g_cur1);
    cudaGetSymbolAddress((void**)&p_cur2, g_cur2);
    cudaGetSymbolAddress((void**)&p_cur3, g_cur3);
    cudaGetSymbolAddress((void**)&p_b0, g_bsum0);
    cudaGetSymbolAddress((void**)&p_b1, g_bsum1);
    cudaGetSymbolAddress((void**)&p_b2, g_bsum2);
    cudaGetSymbolAddress((void**)&p_b3, g_bsum3);
    cudaGetSymbolAddress((void**)&p_sgg, g_src_gg);
    cudaGetSymbolAddress((void**)&p_sh,  g_src_h);
    cudaGetSymbolAddress((void**)&p_sin, g_src_in);
    cudaGetSymbolAddress((void**)&p_sss, g_src_ss);
    cudaGetSymbolAddress((void**)&p_wgg, g_w_gg);
    cudaGetSymbolAddress((void**)&p_wh,  g_w_h);
    cudaGetSymbolAddress((void**)&p_wss, g_w_ss);
    cudaGetSymbolAddress((void**)&p_dinv1, g_dinv1);
    cudaGetSymbolAddress((void**)&p_dinv2, g_dinv2);
    cudaGetSymbolAddress((void**)&p_xg16, g_xg16);
    cudaGetSymbolAddress((void**)&p_x1h,  g_x1h);
    cudaGetSymbolAddress((void**)&p_x2h,  g_x2h);
    cudaGetSymbolAddress((void**)&p_gamex16, g_gamex16);
    cudaGetSymbolAddress((void**)&p_agg1h, g_agg1h);
    cudaGetSymbolAddress((void**)&p_agg2h, g_agg2h);
    cudaGetSymbolAddress((void**)&p_state2h, g_state2h);
    cudaGetSymbolAddress((void**)&p_h1h, g_h1h);
    cudaGetSymbolAddress((void**)&p_h2h, g_h2h);
    cudaGetSymbolAddress((void**)&p_h3h, g_h3h);

    static cudaStream_t s1, s2, s3;
    static cudaEvent_t evFork, evGX, evAGG2, evSAGE, evSS;
    static bool init_done = false;
    if (!init_done) {
        cudaStreamCreateWithFlags(&s1, cudaStreamNonBlocking);
        cudaStreamCreateWithFlags(&s2, cudaStreamNonBlocking);
        cudaStreamCreateWithFlags(&s3, cudaStreamNonBlocking);
        cudaEventCreateWithFlags(&evFork, cudaEventDisableTiming);
        cudaEventCreateWithFlags(&evGX,   cudaEventDisableTiming);
        cudaEventCreateWithFlags(&evAGG2, cudaEventDisableTiming);
        cudaEventCreateWithFlags(&evSAGE, cudaEventDisableTiming);
        cudaEventCreateWithFlags(&evSS,   cudaEventDisableTiming);
        cudaFuncSetAttribute(k_sage_w, cudaFuncAttributeMaxDynamicSharedMemorySize,
                             SAGE_SMEM);
        cudaFuncSetAttribute(k_tag2f_w, cudaFuncAttributeMaxDynamicSharedMemorySize,
                             T2F_SMEM);
        init_done = true;
    }

    const int TB = 256;
    #define NB(n) (((n) + TB - 1) / TB)

    // ---- root: hoisted gg-hist memset (no deps), dtype detect + pack5 ----
    cudaMemsetAsync(p_hgg, 0, (size_t)NN * 4, 0);
    k_detect<<<1, 4>>>((const unsigned*)e_gg, (const unsigned*)e_h,
                       (const unsigned*)e_in, (const unsigned*)e_ss);
    k_pack5<<<NN / TB, TB>>>(x_game, p_xg16);
    cudaEventRecord(evFork, 0);
    cudaStreamWaitEvent(s1, evFork, 0);
    cudaStreamWaitEvent(s2, evFork, 0);
    cudaStreamWaitEvent(s3, evFork, 0);

    // ---- s1: hist-edge CSR ----
    cudaMemsetAsync(p_hh, 0, (size_t)NN * 4, s1);
    k_hist<<<NB(Eh), TB, 0, s1>>>(e_h, Eh, 1, p_hh);
    k_scan1d<<<512, 512, 0, s1>>>(p_hh, p_rh, p_b1, nullptr);
    k_scan23<<<512, 512, 0, s1>>>(p_rh, p_cur1, p_b1, Eh);
    k_place<1><<<NB(Eh), TB, 0, s1>>>(e_h, Eh, 1, p_cur1, p_sh, p_wh, nullptr, ew);

    // ---- s2: tag2 weight conversion + in-edge CSR ----
    k_cvtw<<<64, 256, 0, s2>>>(tag2_w);
    cudaMemsetAsync(p_hin, 0, (size_t)NN * 4, s2);
    k_hist<<<NB(Ein), TB, 0, s2>>>(e_in, Ein, 2, p_hin);
    k_scan1d<<<512, 512, 0, s2>>>(p_hin, p_rin, p_b2, nullptr);
    k_scan23<<<512, 512, 0, s2>>>(p_rin, p_cur2, p_b2, Ein);
    k_place<2><<<NB(Ein), TB, 0, s2>>>(e_in, Ein, 2, p_cur2, p_sin, nullptr, nullptr, nullptr);

    // ---- s3: ss-edge CSR ----
    cudaMemsetAsync(p_hss, 0, (size_t)NN * 4, s3);
    k_hist<<<NB(Ess), TB, 0, s3>>>(e_ss, Ess, 3, p_hss);
    k_scan1d<<<512, 512, 0, s3>>>(p_hss, p_rss, p_b3, p_dinv2);
    k_scan23<<<512, 512, 0, s3>>>(p_rss, p_cur3, p_b3, Ess);
    k_place<0><<<NB(Ess), TB, 0, s3>>>(e_ss, Ess, 3, p_cur3, p_sss, p_wss, p_dinv2, nullptr);
    cudaEventRecord(evSS, s3);

    // ---- s0: gg CSR + TAGConv1 -> gamex fp16 ----
    k_hist<<<NB(Egg), TB>>>(e_gg, Egg, 0, p_hgg);
    k_scan1d<<<512, 512>>>(p_hgg, p_rgg, p_b0, p_dinv1);
    k_scan23<<<512, 512>>>(p_rgg, p_cur0, p_b0, Egg);
    k_place<0><<<NB(Egg), TB>>>(e_gg, Egg, 0, p_cur0, p_sgg, p_wgg, p_dinv1, nullptr);
    k_pull5<<<NN * 8 / TB, TB>>>(p_rgg, p_sgg, p_wgg, p_dinv1, p_xg16, p_x1h);
    k_pull5<<<NN * 8 / TB, TB>>>(p_rgg, p_sgg, p_wgg, p_dinv1, p_x1h, p_x2h);
    k_tag1_p<<<2048, TB>>>(x_game, tag1_w, tag1_b);
    cudaEventRecord(evGX, 0);

    // ---- s1: GraphConv path (needs gamex + h CSR) ----
    cudaStreamWaitEvent(s1, evGX, 0);
    k_pull64<1><<<NN * 16 / TB, TB, 0, s1>>>(p_rh, p_sh, p_wh, nullptr,
                                             p_gamex16, p_agg1h);
    k_gc_w<<<512, TB, 0, s1>>>(x_state, gc_w_rel, gc_b_rel, gc_w_root);

    // ---- s2: SAGE aggregation (needs gamex + in CSR) ----
    cudaStreamWaitEvent(s2, evGX, 0);
    k_pull64<2><<<NN * 16 / TB, TB, 0, s2>>>(p_rin, p_sin, nullptr, nullptr,
                                             p_gamex16, p_agg2h);
    cudaEventRecord(evAGG2, s2);

    // ---- s1: SAGE combine -> state2 fp16 ----
    cudaStreamWaitEvent(s1, evAGG2, 0);
    k_sage_w<<<592, TB, SAGE_SMEM, s1>>>(sage_w_l, sage_b_l, sage_w_r);
    cudaEventRecord(evSAGE, s1);

    // ---- s0: TAGConv2 (needs state2 + ss CSR) + fused final ----
    cudaStreamWaitEvent(0, evSAGE, 0);
    cudaStreamWaitEvent(0, evSS, 0);
    k_pull64<0><<<NN * 16 / TB, TB>>>(p_rss, p_sss, p_wss, p_dinv2, p_state2h, p_h1h);
    k_pull64<0><<<NN * 16 / TB, TB>>>(p_rss, p_sss, p_wss, p_dinv2, p_h1h, p_h2h);
    k_pull64<0><<<NN * 16 / TB, TB>>>(p_rss, p_sss, p_wss, p_dinv2, p_h2h, p_h3h);
    k_tag2f_w<<<444, TB, T2F_SMEM>>>(tag2_b, lin_w, lin_b, (float*)d_out);
    #undef NB
}